// round 9
// baseline (speedup 1.0000x reference)
#include <cuda_runtime.h>
#include <cuda_bf16.h>

#define N 512
#define D 128
#define A 4
#define T 1024
#define RS 520          // s_row stride: conflict-free STS/LDS
#define SEGS 20         // swizzled anchor segment stride (floats)
#define NPOS_MAX 64
#define MARGIN 1.0f
#define EPSF 1e-8f

__device__ double             g_sum;
__device__ unsigned long long g_cnt;
__device__ unsigned int       g_done;

__global__ __launch_bounds__(T, 1) void triplet_k(const float* __restrict__ E,
                                                  const int* __restrict__ lab,
                                                  float* __restrict__ out) {
    __shared__ float        s_ea[A * 8 * SEGS];  // swizzled anchors: [(a*8+s)*20 + e]
    __shared__ float        s_row[A * RS];
    __shared__ float        s_prow[A * NPOS_MAX];
    __shared__ int          s_lab[N];
    __shared__ short        s_pos[A][NPOS_MAX];
    __shared__ int          s_np[A];
    __shared__ double       s_wsum[T / 32];
    __shared__ unsigned int s_wcnt[T / 32];
    __shared__ int          s_last;

    const int i0   = blockIdx.x * A;
    const int tid  = threadIdx.x;
    const int lane = tid & 31;
    const int w    = tid >> 5;            // 32 warps

    if (tid < A) s_np[tid] = 0;
    if (tid < A * D) {                    // stage anchors, swizzled stride-20 layout
        const int a   = tid >> 7;
        const int rem = tid & 127;
        const int s   = rem >> 4;
        const int e   = rem & 15;
        s_ea[(a * 8 + s) * SEGS + e] = E[(i0 + a) * D + rem];
    }
    if (tid < N) s_lab[tid] = lab[tid];
    __syncthreads();

    // positives (threads 0..511, one j each)
    if (tid < N) {
        const int lj = s_lab[tid];
#pragma unroll
        for (int a = 0; a < A; a++) {
            if (tid != i0 + a && lj == s_lab[i0 + a]) {
                int p = atomicAdd(&s_np[a], 1);
                s_pos[a][p] = (short)tid;
            }
        }
    }

    // ---- dot phase: warp w owns rows [16w,16w+16) ----
    // lane = 8*r + s; group r handles rows base+r+{0,4,8,12}; seg s = 16 elems
    {
        const int r = lane >> 3;
        const int s = lane & 7;
        const bool b1 = lane & 1;
        const bool b2 = lane & 2;
        const int base = (w << 4) + r;

        const float* ej0 = E + (base + 0) * D + s * 16;
        const float* ej1 = E + (base + 4) * D + s * 16;
        const float* ej2 = E + (base + 8) * D + s * 16;
        const float* ej3 = E + (base + 12) * D + s * 16;
        const float* ea  = s_ea + s * SEGS;

        float acc[4][4];   // [row slot][anchor]
#pragma unroll
        for (int t = 0; t < 4; t++)
#pragma unroll
            for (int a = 0; a < 4; a++) acc[t][a] = 0.f;

#pragma unroll
        for (int q = 0; q < 4; q++) {
            const float4 v0 = *(const float4*)(ej0 + q * 4);
            const float4 v1 = *(const float4*)(ej1 + q * 4);
            const float4 v2 = *(const float4*)(ej2 + q * 4);
            const float4 v3 = *(const float4*)(ej3 + q * 4);
#pragma unroll
            for (int a = 0; a < 4; a++) {
                const float4 av = *(const float4*)(ea + a * 8 * SEGS + q * 4);
                acc[0][a] = fmaf(v0.x, av.x, acc[0][a]); acc[0][a] = fmaf(v0.y, av.y, acc[0][a]);
                acc[0][a] = fmaf(v0.z, av.z, acc[0][a]); acc[0][a] = fmaf(v0.w, av.w, acc[0][a]);
                acc[1][a] = fmaf(v1.x, av.x, acc[1][a]); acc[1][a] = fmaf(v1.y, av.y, acc[1][a]);
                acc[1][a] = fmaf(v1.z, av.z, acc[1][a]); acc[1][a] = fmaf(v1.w, av.w, acc[1][a]);
                acc[2][a] = fmaf(v2.x, av.x, acc[2][a]); acc[2][a] = fmaf(v2.y, av.y, acc[2][a]);
                acc[2][a] = fmaf(v2.z, av.z, acc[2][a]); acc[2][a] = fmaf(v2.w, av.w, acc[2][a]);
                acc[3][a] = fmaf(v3.x, av.x, acc[3][a]); acc[3][a] = fmaf(v3.y, av.y, acc[3][a]);
                acc[3][a] = fmaf(v3.z, av.z, acc[3][a]); acc[3][a] = fmaf(v3.w, av.w, acc[3][a]);
            }
        }

        // per row slot: packed reduce of 4 anchor dots over the 8-lane group
#pragma unroll
        for (int t = 0; t < 4; t++) {
            const float c0 = acc[t][0], c1 = acc[t][1], c2 = acc[t][2], c3 = acc[t][3];
            float p01 = (b1 ? c1 : c0) + __shfl_xor_sync(0xffffffffu, b1 ? c0 : c1, 1);
            float p23 = (b1 ? c3 : c2) + __shfl_xor_sync(0xffffffffu, b1 ? c2 : c3, 1);
            float qv  = (b2 ? p23 : p01) + __shfl_xor_sync(0xffffffffu, b2 ? p01 : p23, 2);
            qv += __shfl_xor_sync(0xffffffffu, qv, 4);
            if ((lane & 4) == 0)
                s_row[(lane & 3) * RS + base + (t << 2)] = qv;
        }
    }
    __syncthreads();

    // ---- compact positive row values for broadcast access ----
    if (tid < A * NPOS_MAX) {
        const int a = tid >> 6;
        const int p = tid & 63;
        if (p < s_np[a]) s_prow[(a << 6) + p] = s_row[a * RS + s_pos[a][p]];
    }
    __syncthreads();

    // ---- hinge phase: thread owns k; half-split over positives ----
    float lsum = 0.f;
    unsigned int lcnt = 0;
    {
        const int k    = tid & (N - 1);
        const int h    = tid >> 9;
        const int labk = s_lab[k];
        const float tv[A] = { MARGIN - s_row[0 * RS + k], MARGIN - s_row[1 * RS + k],
                              MARGIN - s_row[2 * RS + k], MARGIN - s_row[3 * RS + k] };

#pragma unroll
        for (int a = 0; a < A; a++) {
            if (labk != s_lab[i0 + a]) {
                const int    np = s_np[a];
                const float  ta = tv[a];
                const float* pr = s_prow + (a << 6);
                for (int p = h; p < np; p += 2) {
                    const float v = pr[p] + ta;
                    if (v > 0.f)  lsum += v;
                    if (v > EPSF) lcnt++;
                }
            }
        }
    }

    // ---- block reduction ----
    double dsum = (double)lsum;
#pragma unroll
    for (int o = 16; o > 0; o >>= 1) {
        dsum += __shfl_down_sync(0xffffffffu, dsum, o);
        lcnt += __shfl_down_sync(0xffffffffu, lcnt, o);
    }
    if (lane == 0) { s_wsum[w] = dsum; s_wcnt[w] = lcnt; }
    __syncthreads();

    if (tid == 0) {
        double t = 0.0;
        unsigned int c = 0;
#pragma unroll
        for (int ww = 0; ww < T / 32; ww++) { t += s_wsum[ww]; c += s_wcnt[ww]; }
        if (t != 0.0 || c != 0) {
            atomicAdd(&g_sum, t);
            atomicAdd(&g_cnt, (unsigned long long)c);
        }
        __threadfence();
        const unsigned int d = atomicAdd(&g_done, 1u);
        s_last = (d == gridDim.x - 1);
    }
    __syncthreads();

    if (s_last && tid == 0) {
        const double             s = atomicAdd(&g_sum, 0.0);
        const unsigned long long c = atomicAdd(&g_cnt, 0ULL);
        out[0] = (float)(s / ((double)c + (double)EPSF));
        g_sum  = 0.0;
        g_cnt  = 0ULL;
        atomicExch(&g_done, 0u);
    }
}

extern "C" void kernel_launch(void* const* d_in, const int* in_sizes, int n_in,
                              void* d_out, int out_size) {
    const float* E   = (const float*)d_in[0];
    const int*   lab = (const int*)d_in[1];
    float*       out = (float*)d_out;

    triplet_k<<<N / A, T>>>(E, lab, out);
}

// round 10
// speedup vs baseline: 1.2521x; 1.2521x over previous
#include <cuda_runtime.h>
#include <cuda_bf16.h>

#define N 512
#define D 128
#define A 4
#define T 1024
#define RS 520          // s_row stride: conflict-free STS/LDS
#define NPOS_MAX 64
#define MARGIN 1.0f
#define EPSF 1e-8f

__device__ double             g_sum;
__device__ unsigned long long g_cnt;
__device__ unsigned int       g_done;

__global__ __launch_bounds__(T, 1) void triplet_k(const float* __restrict__ E,
                                                  const int* __restrict__ lab,
                                                  float* __restrict__ out) {
    __shared__ float        s_ea[A * D];          // staged anchors (plain layout)
    __shared__ float        s_row[A * RS];
    __shared__ float        s_prow[A * NPOS_MAX];
    __shared__ int          s_lab[N];
    __shared__ short        s_pos[A][NPOS_MAX];
    __shared__ int          s_np[A];
    __shared__ double       s_wsum[T / 32];
    __shared__ unsigned int s_wcnt[T / 32];
    __shared__ int          s_last;

    const int i0   = blockIdx.x * A;
    const int tid  = threadIdx.x;
    const int lane = tid & 31;
    const int w    = tid >> 5;            // 32 warps

    if (tid < A) s_np[tid] = 0;
    if (tid < A * D) s_ea[tid] = E[i0 * D + tid];
    if (tid < N)     s_lab[tid] = lab[tid];
    __syncthreads();

    // positives (threads 0..511, one j each)
    if (tid < N) {
        const int lj = s_lab[tid];
#pragma unroll
        for (int a = 0; a < A; a++) {
            if (tid != i0 + a && lj == s_lab[i0 + a]) {
                int p = atomicAdd(&s_np[a], 1);
                s_pos[a][p] = (short)tid;
            }
        }
    }

    // ---- dot phase: warp w owns rows [16w,16w+16); 8-lane group per row-slot ----
    // lane = 8*r + s; rows j = 16w + 4*pass + r; segment s covers floats [4s+32q, +3]
    {
        const int r = lane >> 3;
        const int s = lane & 7;
        const bool b1 = lane & 1;
        const bool b2 = lane & 2;
        const int base = (w << 4) + r;

        const float* ej0 = E + (base + 0) * D + s * 4;
        const float* ej1 = E + (base + 4) * D + s * 4;
        const float* ej2 = E + (base + 8) * D + s * 4;
        const float* ej3 = E + (base + 12) * D + s * 4;
        const float* ea  = s_ea + s * 4;

        float acc[4][4];   // [pass][anchor]
#pragma unroll
        for (int t = 0; t < 4; t++)
#pragma unroll
            for (int a = 0; a < 4; a++) acc[t][a] = 0.f;

#pragma unroll
        for (int q = 0; q < 4; q++) {
            // anchor segment-q loaded ONCE (was: reloaded every pass)
            const float4 a0 = *(const float4*)(ea + 0 * D + q * 32);
            const float4 a1 = *(const float4*)(ea + 1 * D + q * 32);
            const float4 a2 = *(const float4*)(ea + 2 * D + q * 32);
            const float4 a3 = *(const float4*)(ea + 3 * D + q * 32);
            // 4 independent coalesced row loads (128 B per row-group: 4 wavefronts)
            const float4 v0 = *(const float4*)(ej0 + q * 32);
            const float4 v1 = *(const float4*)(ej1 + q * 32);
            const float4 v2 = *(const float4*)(ej2 + q * 32);
            const float4 v3 = *(const float4*)(ej3 + q * 32);

            acc[0][0] = fmaf(v0.x, a0.x, acc[0][0]); acc[0][0] = fmaf(v0.y, a0.y, acc[0][0]);
            acc[0][0] = fmaf(v0.z, a0.z, acc[0][0]); acc[0][0] = fmaf(v0.w, a0.w, acc[0][0]);
            acc[0][1] = fmaf(v0.x, a1.x, acc[0][1]); acc[0][1] = fmaf(v0.y, a1.y, acc[0][1]);
            acc[0][1] = fmaf(v0.z, a1.z, acc[0][1]); acc[0][1] = fmaf(v0.w, a1.w, acc[0][1]);
            acc[0][2] = fmaf(v0.x, a2.x, acc[0][2]); acc[0][2] = fmaf(v0.y, a2.y, acc[0][2]);
            acc[0][2] = fmaf(v0.z, a2.z, acc[0][2]); acc[0][2] = fmaf(v0.w, a2.w, acc[0][2]);
            acc[0][3] = fmaf(v0.x, a3.x, acc[0][3]); acc[0][3] = fmaf(v0.y, a3.y, acc[0][3]);
            acc[0][3] = fmaf(v0.z, a3.z, acc[0][3]); acc[0][3] = fmaf(v0.w, a3.w, acc[0][3]);

            acc[1][0] = fmaf(v1.x, a0.x, acc[1][0]); acc[1][0] = fmaf(v1.y, a0.y, acc[1][0]);
            acc[1][0] = fmaf(v1.z, a0.z, acc[1][0]); acc[1][0] = fmaf(v1.w, a0.w, acc[1][0]);
            acc[1][1] = fmaf(v1.x, a1.x, acc[1][1]); acc[1][1] = fmaf(v1.y, a1.y, acc[1][1]);
            acc[1][1] = fmaf(v1.z, a1.z, acc[1][1]); acc[1][1] = fmaf(v1.w, a1.w, acc[1][1]);
            acc[1][2] = fmaf(v1.x, a2.x, acc[1][2]); acc[1][2] = fmaf(v1.y, a2.y, acc[1][2]);
            acc[1][2] = fmaf(v1.z, a2.z, acc[1][2]); acc[1][2] = fmaf(v1.w, a2.w, acc[1][2]);
            acc[1][3] = fmaf(v1.x, a3.x, acc[1][3]); acc[1][3] = fmaf(v1.y, a3.y, acc[1][3]);
            acc[1][3] = fmaf(v1.z, a3.z, acc[1][3]); acc[1][3] = fmaf(v1.w, a3.w, acc[1][3]);

            acc[2][0] = fmaf(v2.x, a0.x, acc[2][0]); acc[2][0] = fmaf(v2.y, a0.y, acc[2][0]);
            acc[2][0] = fmaf(v2.z, a0.z, acc[2][0]); acc[2][0] = fmaf(v2.w, a0.w, acc[2][0]);
            acc[2][1] = fmaf(v2.x, a1.x, acc[2][1]); acc[2][1] = fmaf(v2.y, a1.y, acc[2][1]);
            acc[2][1] = fmaf(v2.z, a1.z, acc[2][1]); acc[2][1] = fmaf(v2.w, a1.w, acc[2][1]);
            acc[2][2] = fmaf(v2.x, a2.x, acc[2][2]); acc[2][2] = fmaf(v2.y, a2.y, acc[2][2]);
            acc[2][2] = fmaf(v2.z, a2.z, acc[2][2]); acc[2][2] = fmaf(v2.w, a2.w, acc[2][2]);
            acc[2][3] = fmaf(v2.x, a3.x, acc[2][3]); acc[2][3] = fmaf(v2.y, a3.y, acc[2][3]);
            acc[2][3] = fmaf(v2.z, a3.z, acc[2][3]); acc[2][3] = fmaf(v2.w, a3.w, acc[2][3]);

            acc[3][0] = fmaf(v3.x, a0.x, acc[3][0]); acc[3][0] = fmaf(v3.y, a0.y, acc[3][0]);
            acc[3][0] = fmaf(v3.z, a0.z, acc[3][0]); acc[3][0] = fmaf(v3.w, a0.w, acc[3][0]);
            acc[3][1] = fmaf(v3.x, a1.x, acc[3][1]); acc[3][1] = fmaf(v3.y, a1.y, acc[3][1]);
            acc[3][1] = fmaf(v3.z, a1.z, acc[3][1]); acc[3][1] = fmaf(v3.w, a1.w, acc[3][1]);
            acc[3][2] = fmaf(v3.x, a2.x, acc[3][2]); acc[3][2] = fmaf(v3.y, a2.y, acc[3][2]);
            acc[3][2] = fmaf(v3.z, a2.z, acc[3][2]); acc[3][2] = fmaf(v3.w, a2.w, acc[3][2]);
            acc[3][3] = fmaf(v3.x, a3.x, acc[3][3]); acc[3][3] = fmaf(v3.y, a3.y, acc[3][3]);
            acc[3][3] = fmaf(v3.z, a3.z, acc[3][3]); acc[3][3] = fmaf(v3.w, a3.w, acc[3][3]);
        }

        // per pass: packed reduce of 4 anchor dots over the 8-lane group
#pragma unroll
        for (int t = 0; t < 4; t++) {
            const float c0 = acc[t][0], c1 = acc[t][1], c2 = acc[t][2], c3 = acc[t][3];
            float p01 = (b1 ? c1 : c0) + __shfl_xor_sync(0xffffffffu, b1 ? c0 : c1, 1);
            float p23 = (b1 ? c3 : c2) + __shfl_xor_sync(0xffffffffu, b1 ? c2 : c3, 1);
            float qv  = (b2 ? p23 : p01) + __shfl_xor_sync(0xffffffffu, b2 ? p01 : p23, 2);
            qv += __shfl_xor_sync(0xffffffffu, qv, 4);
            if ((lane & 4) == 0)
                s_row[(lane & 3) * RS + base + (t << 2)] = qv;
        }
    }
    __syncthreads();

    // ---- compact positive row values for broadcast access ----
    if (tid < A * NPOS_MAX) {
        const int a = tid >> 6;
        const int p = tid & 63;
        if (p < s_np[a]) s_prow[(a << 6) + p] = s_row[a * RS + s_pos[a][p]];
    }
    __syncthreads();

    // ---- hinge phase: thread owns k; half-split over positives ----
    float lsum = 0.f;
    unsigned int lcnt = 0;
    {
        const int k    = tid & (N - 1);
        const int h    = tid >> 9;
        const int labk = s_lab[k];
        const float tv[A] = { MARGIN - s_row[0 * RS + k], MARGIN - s_row[1 * RS + k],
                              MARGIN - s_row[2 * RS + k], MARGIN - s_row[3 * RS + k] };

#pragma unroll
        for (int a = 0; a < A; a++) {
            if (labk != s_lab[i0 + a]) {
                const int    np = s_np[a];
                const float  ta = tv[a];
                const float* pr = s_prow + (a << 6);
                for (int p = h; p < np; p += 2) {
                    const float v = pr[p] + ta;
                    if (v > 0.f)  lsum += v;
                    if (v > EPSF) lcnt++;
                }
            }
        }
    }

    // ---- block reduction ----
    double dsum = (double)lsum;
#pragma unroll
    for (int o = 16; o > 0; o >>= 1) {
        dsum += __shfl_down_sync(0xffffffffu, dsum, o);
        lcnt += __shfl_down_sync(0xffffffffu, lcnt, o);
    }
    if (lane == 0) { s_wsum[w] = dsum; s_wcnt[w] = lcnt; }
    __syncthreads();

    if (tid == 0) {
        double t = 0.0;
        unsigned int c = 0;
#pragma unroll
        for (int ww = 0; ww < T / 32; ww++) { t += s_wsum[ww]; c += s_wcnt[ww]; }
        if (t != 0.0 || c != 0) {
            atomicAdd(&g_sum, t);
            atomicAdd(&g_cnt, (unsigned long long)c);
        }
        __threadfence();
        const unsigned int d = atomicAdd(&g_done, 1u);
        s_last = (d == gridDim.x - 1);
    }
    __syncthreads();

    if (s_last && tid == 0) {
        const double             s = atomicAdd(&g_sum, 0.0);
        const unsigned long long c = atomicAdd(&g_cnt, 0ULL);
        out[0] = (float)(s / ((double)c + (double)EPSF));
        g_sum  = 0.0;
        g_cnt  = 0ULL;
        atomicExch(&g_done, 0u);
    }
}

extern "C" void kernel_launch(void* const* d_in, const int* in_sizes, int n_in,
                              void* d_out, int out_size) {
    const float* E   = (const float*)d_in[0];
    const int*   lab = (const int*)d_in[1];
    float*       out = (float*)d_out;

    triplet_k<<<N / A, T>>>(E, lab, out);
}

// round 11
// speedup vs baseline: 1.2548x; 1.0021x over previous
#include <cuda_runtime.h>
#include <cuda_bf16.h>

#define N 512
#define D 128
#define A 2
#define T 512
#define GRID (N / A)    // 256 CTAs, 2 per SM
#define RS 520
#define NPOS_MAX 64
#define MARGIN 1.0f
#define EPSF 1e-8f

__device__ double             g_sum;
__device__ unsigned long long g_cnt;
__device__ unsigned int       g_done;

__global__ __launch_bounds__(T, 2) void triplet_k(const float* __restrict__ E,
                                                  const int* __restrict__ lab,
                                                  float* __restrict__ out) {
    __shared__ float        s_ea[A * D];
    __shared__ float        s_row[A * RS];
    __shared__ float        s_prow[A * NPOS_MAX];
    __shared__ int          s_lab[N];
    __shared__ short        s_pos[A][NPOS_MAX];
    __shared__ int          s_np[A];
    __shared__ double       s_wsum[T / 32];
    __shared__ unsigned int s_wcnt[T / 32];
    __shared__ int          s_last;

    const int i0   = blockIdx.x * A;
    const int tid  = threadIdx.x;
    const int lane = tid & 31;
    const int w    = tid >> 5;            // 16 warps

    if (tid < A) s_np[tid] = 0;
    if (tid < A * D) s_ea[tid] = E[i0 * D + tid];
    if (tid < N)     s_lab[tid] = lab[tid];
    __syncthreads();

    // positives (threads 0..511, one j each)
    {
        const int lj = s_lab[tid];
#pragma unroll
        for (int a = 0; a < A; a++) {
            if (tid != i0 + a && lj == s_lab[i0 + a]) {
                int p = atomicAdd(&s_np[a], 1);
                s_pos[a][p] = (short)tid;
            }
        }
    }

    // ---- dot phase: warp w owns rows [32w, 32w+32); 8-lane group per row-slot ----
    // lane = 8*r + s; rows j = 32w + 16g + 4t + r; segment s covers floats 4s+32q..+3
    {
        const int r = lane >> 3;
        const int s = lane & 7;
        const bool b1 = lane & 1;
        const float* ea = s_ea + s * 4;

#pragma unroll
        for (int g = 0; g < 2; g++) {
            const int base = (w << 5) + (g << 4) + r;
            const float* ej0 = E + (base + 0) * D + s * 4;
            const float* ej1 = E + (base + 4) * D + s * 4;
            const float* ej2 = E + (base + 8) * D + s * 4;
            const float* ej3 = E + (base + 12) * D + s * 4;

            float acc[4][2];
#pragma unroll
            for (int t = 0; t < 4; t++) { acc[t][0] = 0.f; acc[t][1] = 0.f; }

#pragma unroll
            for (int q = 0; q < 4; q++) {
                const float4 a0 = *(const float4*)(ea + 0 * D + q * 32);
                const float4 a1 = *(const float4*)(ea + 1 * D + q * 32);
                const float4 v0 = *(const float4*)(ej0 + q * 32);
                const float4 v1 = *(const float4*)(ej1 + q * 32);
                const float4 v2 = *(const float4*)(ej2 + q * 32);
                const float4 v3 = *(const float4*)(ej3 + q * 32);

                acc[0][0] = fmaf(v0.x, a0.x, acc[0][0]); acc[0][0] = fmaf(v0.y, a0.y, acc[0][0]);
                acc[0][0] = fmaf(v0.z, a0.z, acc[0][0]); acc[0][0] = fmaf(v0.w, a0.w, acc[0][0]);
                acc[0][1] = fmaf(v0.x, a1.x, acc[0][1]); acc[0][1] = fmaf(v0.y, a1.y, acc[0][1]);
                acc[0][1] = fmaf(v0.z, a1.z, acc[0][1]); acc[0][1] = fmaf(v0.w, a1.w, acc[0][1]);

                acc[1][0] = fmaf(v1.x, a0.x, acc[1][0]); acc[1][0] = fmaf(v1.y, a0.y, acc[1][0]);
                acc[1][0] = fmaf(v1.z, a0.z, acc[1][0]); acc[1][0] = fmaf(v1.w, a0.w, acc[1][0]);
                acc[1][1] = fmaf(v1.x, a1.x, acc[1][1]); acc[1][1] = fmaf(v1.y, a1.y, acc[1][1]);
                acc[1][1] = fmaf(v1.z, a1.z, acc[1][1]); acc[1][1] = fmaf(v1.w, a1.w, acc[1][1]);

                acc[2][0] = fmaf(v2.x, a0.x, acc[2][0]); acc[2][0] = fmaf(v2.y, a0.y, acc[2][0]);
                acc[2][0] = fmaf(v2.z, a0.z, acc[2][0]); acc[2][0] = fmaf(v2.w, a0.w, acc[2][0]);
                acc[2][1] = fmaf(v2.x, a1.x, acc[2][1]); acc[2][1] = fmaf(v2.y, a1.y, acc[2][1]);
                acc[2][1] = fmaf(v2.z, a1.z, acc[2][1]); acc[2][1] = fmaf(v2.w, a1.w, acc[2][1]);

                acc[3][0] = fmaf(v3.x, a0.x, acc[3][0]); acc[3][0] = fmaf(v3.y, a0.y, acc[3][0]);
                acc[3][0] = fmaf(v3.z, a0.z, acc[3][0]); acc[3][0] = fmaf(v3.w, a0.w, acc[3][0]);
                acc[3][1] = fmaf(v3.x, a1.x, acc[3][1]); acc[3][1] = fmaf(v3.y, a1.y, acc[3][1]);
                acc[3][1] = fmaf(v3.z, a1.z, acc[3][1]); acc[3][1] = fmaf(v3.w, a1.w, acc[3][1]);
            }

            // packed 2-anchor reduce over 8-lane group: xor1 packed, xor2, xor4
#pragma unroll
            for (int t = 0; t < 4; t++) {
                const float c0 = acc[t][0], c1 = acc[t][1];
                float p01 = (b1 ? c1 : c0) + __shfl_xor_sync(0xffffffffu, b1 ? c0 : c1, 1);
                p01 += __shfl_xor_sync(0xffffffffu, p01, 2);
                p01 += __shfl_xor_sync(0xffffffffu, p01, 4);
                // lane 8r+a (a<2) holds dot(anchor a, row base+4t)
                if ((lane & 6) == 0)
                    s_row[(lane & 1) * RS + base + (t << 2)] = p01;
            }
        }
    }
    __syncthreads();

    // ---- compact positive row values ----
    if (tid < A * NPOS_MAX) {
        const int a = tid >> 6;
        const int p = tid & 63;
        if (p < s_np[a]) s_prow[(a << 6) + p] = s_row[a * RS + s_pos[a][p]];
    }
    __syncthreads();

    // ---- hinge phase: thread owns k = tid ----
    float lsum = 0.f;
    unsigned int lcnt = 0;
    {
        const int k    = tid;
        const int labk = s_lab[k];
        const float tv[A] = { MARGIN - s_row[0 * RS + k], MARGIN - s_row[1 * RS + k] };

#pragma unroll
        for (int a = 0; a < A; a++) {
            if (labk != s_lab[i0 + a]) {
                const int    np = s_np[a];
                const float  ta = tv[a];
                const float* pr = s_prow + (a << 6);
                for (int p = 0; p < np; p++) {
                    const float v = pr[p] + ta;
                    if (v > 0.f)  lsum += v;
                    if (v > EPSF) lcnt++;
                }
            }
        }
    }

    // ---- block reduction ----
    double dsum = (double)lsum;
#pragma unroll
    for (int o = 16; o > 0; o >>= 1) {
        dsum += __shfl_down_sync(0xffffffffu, dsum, o);
        lcnt += __shfl_down_sync(0xffffffffu, lcnt, o);
    }
    if (lane == 0) { s_wsum[w] = dsum; s_wcnt[w] = lcnt; }
    __syncthreads();

    if (tid == 0) {
        double t = 0.0;
        unsigned int c = 0;
#pragma unroll
        for (int ww = 0; ww < T / 32; ww++) { t += s_wsum[ww]; c += s_wcnt[ww]; }
        if (t != 0.0 || c != 0) {
            atomicAdd(&g_sum, t);
            atomicAdd(&g_cnt, (unsigned long long)c);
        }
        __threadfence();
        const unsigned int d = atomicAdd(&g_done, 1u);
        s_last = (d == GRID - 1);
    }
    __syncthreads();

    if (s_last && tid == 0) {
        const double             s = atomicAdd(&g_sum, 0.0);
        const unsigned long long c = atomicAdd(&g_cnt, 0ULL);
        out[0] = (float)(s / ((double)c + (double)EPSF));
        g_sum  = 0.0;
        g_cnt  = 0ULL;
        atomicExch(&g_done, 0u);
    }
}

extern "C" void kernel_launch(void* const* d_in, const int* in_sizes, int n_in,
                              void* d_out, int out_size) {
    const float* E   = (const float*)d_in[0];
    const int*   lab = (const int*)d_in[1];
    float*       out = (float*)d_out;

    triplet_k<<<GRID, T>>>(E, lab, out);
}